// round 6
// baseline (speedup 1.0000x reference)
#include <cuda_runtime.h>
#include <cuda_bf16.h>
#include <math.h>

#define NN 200000
#define DD 128
#define G3 384
#define MD 12
#define TM 64
#define NT (NN / TM)            // 3125 row tiles (exact)
#define RB ((NN + 255) / 256)   // 782
#define ALD 132                 // A smem leading dim (row-major, padded)
#define BLD 136                 // B smem leading dim (k-major, padded)
#define SMEMB ((TM * ALD + DD * BLD) * 4)

// ---------------- scratch (device globals: allocation-free) ----------------
__device__ __align__(256) float g_x [(size_t)NN * DD];   // normalized features
__device__ __align__(256) float g_gi[(size_t)NN * G3];   // x @ W_ih^T + b_ih
__device__ __align__(256) float g_gh[(size_t)NN * G3];   // per-step h @ W_hh^T
__device__ __align__(256) float g_h [(size_t)NN * DD];   // hidden (permuted order)
__device__ float g_psum[RB * DD];
__device__ float g_psq [RB * DD];
__device__ float g_a[DD], g_b[DD];                       // folded BN affine
__device__ int   g_cnt[MD + 1], g_cur[MD + 1], g_act[MD];
__device__ int   g_perm[NN];                             // descending-degree order
__device__ int   g_mtype;                                // 0=u8 1=i32 2=f32 3=bf16

__device__ __forceinline__ float sigm(float x) { return 1.0f / (1.0f + expf(-x)); }

// ---------------- mask dtype detection ----------------
__global__ void k_detect(const unsigned char* __restrict__ m) {
    __shared__ int has3F, nzNot0, nz0;
    if (threadIdx.x == 0) { has3F = 0; nzNot0 = 0; nz0 = 0; }
    __syncthreads();
    for (int i = threadIdx.x; i < 16384; i += 256) {
        unsigned char b = m[i];
        if (b == 0x3F) atomicOr(&has3F, 1);
        if (b != 0 && (i & 3) != 0) atomicOr(&nzNot0, 1);
        if (b != 0 && (i & 3) == 0) atomicOr(&nz0, 1);
    }
    __syncthreads();
    if (threadIdx.x == 0) {
        int ty;
        if (has3F && nz0)      ty = 3;   // bf16 (0x3F80 pattern spans even+odd offsets)
        else if (has3F)        ty = 2;   // f32  (0x3F only at off%4==3, off%4==0 always 0)
        else if (nzNot0)       ty = 0;   // u8 bool (ones at arbitrary offsets)
        else                   ty = 1;   // i32 (nonzero only at off%4==0)
        g_mtype = ty;
    }
}

__device__ __forceinline__ int deg_any(const void* m, int n) {
    int ty = g_mtype;
    int d = 0;
    if (ty == 1) {
        const int* p = (const int*)m + (size_t)n * MD;
#pragma unroll
        for (int j = 0; j < MD; ++j) d += (p[j] != 0);
    } else if (ty == 0) {
        const unsigned char* p = (const unsigned char*)m + (size_t)n * MD;
#pragma unroll
        for (int j = 0; j < MD; ++j) d += (p[j] != 0);
    } else if (ty == 2) {
        const float* p = (const float*)m + (size_t)n * MD;
#pragma unroll
        for (int j = 0; j < MD; ++j) d += (p[j] != 0.0f);
    } else {
        const unsigned short* p = (const unsigned short*)m + (size_t)n * MD;
#pragma unroll
        for (int j = 0; j < MD; ++j) d += ((p[j] & 0x7FFF) != 0);
    }
    return d;
}

// ---------------- setup kernels ----------------
__global__ void k_zero() {
    int t = threadIdx.x;
    if (t <= MD) g_cnt[t] = 0;
}

// per-block partial column sums (deterministic fixed-order final reduce)
__global__ void k_stats(const float* __restrict__ feat) {
    int col = threadIdx.x;           // 128 threads
    int r0 = blockIdx.x * 256;
    int rend = min(r0 + 256, NN);
    float s = 0.f, q = 0.f;
    for (int r = r0; r < rend; ++r) {
        float v = feat[(size_t)r * DD + col];
        s += v; q += v * v;
    }
    g_psum[blockIdx.x * DD + col] = s;
    g_psq [blockIdx.x * DD + col] = q;
}

__global__ void k_deg(const void* __restrict__ mask) {
    __shared__ int c[MD + 1];
    int tid = threadIdx.x;
    if (tid <= MD) c[tid] = 0;
    __syncthreads();
    int n = blockIdx.x * 256 + tid;
    if (n < NN) atomicAdd(&c[deg_any(mask, n)], 1);
    __syncthreads();
    if (tid <= MD && c[tid] > 0) atomicAdd(&g_cnt[tid], c[tid]);
}

__global__ void k_finalize(const float* __restrict__ gamma, const float* __restrict__ beta) {
    int t = threadIdx.x;   // 128 threads
    float s = 0.f, q = 0.f;
    for (int b = 0; b < RB; ++b) { s += g_psum[b * DD + t]; q += g_psq[b * DD + t]; }
    float mu = s * (1.0f / NN);
    float var = q * (1.0f / NN) - mu * mu;
    float rs = rsqrtf(var + 1e-5f);
    float a = rs * gamma[t];
    g_a[t] = a;
    g_b[t] = beta[t] - mu * a;
    if (t == 0) {
        int suf = 0;
        for (int d = MD; d >= 0; --d) { g_cur[d] = suf; suf += g_cnt[d]; }
        for (int sdx = 0; sdx < MD; ++sdx) g_act[sdx] = g_cur[sdx];  // A_t = #{deg>t}
    }
}

__global__ void k_scatter(const void* __restrict__ mask) {
    int n = blockIdx.x * 256 + threadIdx.x;
    if (n >= NN) return;
    int pos = atomicAdd(&g_cur[deg_any(mask, n)], 1);
    g_perm[pos] = n;
}

__global__ void k_norm(const float* __restrict__ feat) {
    int i = blockIdx.x * 256 + threadIdx.x;          // float4 index
    if (i >= NN * DD / 4) return;
    float4 v = ((const float4*)feat)[i];
    int c = (i & 31) * 4;
    v.x = v.x * g_a[c + 0] + g_b[c + 0];
    v.y = v.y * g_a[c + 1] + g_b[c + 1];
    v.z = v.z * g_a[c + 2] + g_b[c + 2];
    v.w = v.w * g_a[c + 3] + g_b[c + 3];
    ((float4*)g_x)[i] = v;
}

// ---------------- shared GEMM pieces: 64 rows x 128 cols x K=128 ----------------
__device__ __forceinline__ void ldA(float* As, const float* __restrict__ Ag, int tid) {
#pragma unroll
    for (int it = 0; it < 8; ++it) {
        int idx = tid + it * 256;
        int row = idx >> 5;
        int k0 = (idx & 31) << 2;
        float4 v = *(const float4*)(Ag + (size_t)row * DD + k0);
        *(float4*)(As + row * ALD + k0) = v;
    }
}
__device__ __forceinline__ void ldA_gather(float* As, const float* __restrict__ Abase,
                                           const int* __restrict__ rows, int tid) {
#pragma unroll
    for (int it = 0; it < 8; ++it) {
        int idx = tid + it * 256;
        int row = idx >> 5;
        int k0 = (idx & 31) << 2;
        float4 v = *(const float4*)(Abase + (size_t)rows[row] * DD + k0);
        *(float4*)(As + row * ALD + k0) = v;
    }
}
// B: global W chunk [128 out-cols][128 k] row-major -> Bs[k][col]
__device__ __forceinline__ void ldB(float* Bs, const float* __restrict__ Wg, int tid) {
#pragma unroll
    for (int it = 0; it < 16; ++it) {
        int idx = tid + it * 256;
        int col = (idx & 7) + ((idx >> 8) << 3);
        int kq = (idx >> 3) & 31;
        float4 v = *(const float4*)(Wg + (size_t)col * DD + (kq << 2));
        int k0 = kq << 2;
        Bs[(k0 + 0) * BLD + col] = v.x;
        Bs[(k0 + 1) * BLD + col] = v.y;
        Bs[(k0 + 2) * BLD + col] = v.z;
        Bs[(k0 + 3) * BLD + col] = v.w;
    }
}
__device__ __forceinline__ void mmacc(const float* As, const float* Bs,
                                      float acc[8][4], int tid) {
    int tx = tid & 31, ty = tid >> 5;
    int c0 = tx << 2, r0 = ty << 3;
#pragma unroll 4
    for (int k = 0; k < DD; ++k) {
        float4 bb = *(const float4*)(Bs + k * BLD + c0);
        float a[8];
#pragma unroll
        for (int r = 0; r < 8; ++r) a[r] = As[(r0 + r) * ALD + k];
#pragma unroll
        for (int r = 0; r < 8; ++r) {
            acc[r][0] += a[r] * bb.x;
            acc[r][1] += a[r] * bb.y;
            acc[r][2] += a[r] * bb.z;
            acc[r][3] += a[r] * bb.w;
        }
    }
}

// ---------------- GEMM kernels ----------------
__global__ void __launch_bounds__(256) k_gi(const float* __restrict__ Wih,
                                            const float* __restrict__ bih) {
    extern __shared__ float sm[];
    float* As = sm; float* Bs = sm + TM * ALD;
    int rt = blockIdx.x, g = blockIdx.y, tid = threadIdx.x;
    ldA(As, g_x + (size_t)rt * TM * DD, tid);
    ldB(Bs, Wih + (size_t)g * DD * DD, tid);
    __syncthreads();
    float acc[8][4] = {};
    mmacc(As, Bs, acc, tid);
    int tx = tid & 31, ty = tid >> 5;
    int c0 = tx << 2, r0 = ty << 3;
    float4 bb = *(const float4*)(bih + g * DD + c0);
#pragma unroll
    for (int r = 0; r < 8; ++r) {
        float4 v = make_float4(acc[r][0] + bb.x, acc[r][1] + bb.y,
                               acc[r][2] + bb.z, acc[r][3] + bb.w);
        *(float4*)(g_gi + (size_t)(rt * TM + r0 + r) * G3 + g * DD + c0) = v;
    }
}

__global__ void __launch_bounds__(256) k_gh(const float* __restrict__ Whh, int t) {
    if (blockIdx.x * TM >= g_act[t]) return;
    extern __shared__ float sm[];
    float* As = sm; float* Bs = sm + TM * ALD;
    int rt = blockIdx.x, g = blockIdx.y, tid = threadIdx.x;
    ldA(As, g_h + (size_t)rt * TM * DD, tid);
    ldB(Bs, Whh + (size_t)g * DD * DD, tid);
    __syncthreads();
    float acc[8][4] = {};
    mmacc(As, Bs, acc, tid);
    int tx = tid & 31, ty = tid >> 5;
    int c0 = tx << 2, r0 = ty << 3;
#pragma unroll
    for (int r = 0; r < 8; ++r) {
        float4 v = make_float4(acc[r][0], acc[r][1], acc[r][2], acc[r][3]);
        *(float4*)(g_gh + (size_t)(rt * TM + r0 + r) * G3 + g * DD + c0) = v;
    }
}

__global__ void __launch_bounds__(256) k_final(const float* __restrict__ Wself,
                                               const float* __restrict__ Wneigh,
                                               float* __restrict__ out) {
    extern __shared__ float sm[];
    float* As = sm; float* Bs = sm + TM * ALD;
    int rt = blockIdx.x, tid = threadIdx.x;
    int base = rt * TM;
    float acc[8][4] = {};
    ldA_gather(As, g_x, g_perm + base, tid);
    ldB(Bs, Wself, tid);
    __syncthreads();
    mmacc(As, Bs, acc, tid);
    __syncthreads();
    ldA(As, g_h + (size_t)base * DD, tid);
    ldB(Bs, Wneigh, tid);
    __syncthreads();
    mmacc(As, Bs, acc, tid);
    int tx = tid & 31, ty = tid >> 5;
    int c0 = tx << 2, r0 = ty << 3;
#pragma unroll
    for (int r = 0; r < 8; ++r) {
        int n = g_perm[base + r0 + r];
        float4 v = make_float4(acc[r][0], acc[r][1], acc[r][2], acc[r][3]);
        *(float4*)(out + (size_t)n * DD + c0) = v;
    }
}

// ---------------- GRU elementwise ----------------
__global__ void k_step0(const int* __restrict__ src, const float* __restrict__ bhh) {
    int i = blockIdx.x * 2 + (threadIdx.x >> 7);
    int c = threadIdx.x & 127;
    if (i >= NN) return;
    float h = 0.f;
    if (i < g_act[0]) {
        int n = g_perm[i];
        int s = src[(size_t)n * MD];
        const float* gi = g_gi + (size_t)s * G3;
        float r = sigm(gi[c] + bhh[c]);
        float z = sigm(gi[c + 128] + bhh[c + 128]);
        float nn = tanhf(gi[c + 256] + r * bhh[c + 256]);
        h = (1.f - z) * nn;
    }
    g_h[(size_t)i * DD + c] = h;
}

__global__ void k_gate(const int* __restrict__ src, const float* __restrict__ bhh, int t) {
    int i = blockIdx.x * 2 + (threadIdx.x >> 7);
    int c = threadIdx.x & 127;
    if (i >= g_act[t]) return;
    int n = g_perm[i];
    int s = src[(size_t)n * MD + t];
    const float* gi = g_gi + (size_t)s * G3;
    const float* gh = g_gh + (size_t)i * G3;
    float r = sigm(gi[c] + gh[c] + bhh[c]);
    float z = sigm(gi[c + 128] + gh[c + 128] + bhh[c + 128]);
    float nn = tanhf(gi[c + 256] + r * (gh[c + 256] + bhh[c + 256]));
    float hp = g_h[(size_t)i * DD + c];
    g_h[(size_t)i * DD + c] = (1.f - z) * nn + z * hp;
}

// ---------------- launch ----------------
extern "C" void kernel_launch(void* const* d_in, const int* in_sizes, int n_in,
                              void* d_out, int out_size) {
    const float* feat   = (const float*)d_in[0];
    const float* gamma  = (const float*)d_in[1];
    const float* beta   = (const float*)d_in[2];
    const float* W_ih   = (const float*)d_in[3];
    const float* W_hh   = (const float*)d_in[4];
    const float* b_ih   = (const float*)d_in[5];
    const float* b_hh   = (const float*)d_in[6];
    const float* W_self = (const float*)d_in[7];
    const float* W_neigh= (const float*)d_in[8];
    const int*   src    = (const int*)d_in[9];
    const void*  mask   = (const void*)d_in[10];
    float* out = (float*)d_out;

    cudaFuncSetAttribute(k_gi,    cudaFuncAttributeMaxDynamicSharedMemorySize, SMEMB);
    cudaFuncSetAttribute(k_gh,    cudaFuncAttributeMaxDynamicSharedMemorySize, SMEMB);
    cudaFuncSetAttribute(k_final, cudaFuncAttributeMaxDynamicSharedMemorySize, SMEMB);

    k_detect<<<1, 256>>>((const unsigned char*)mask);
    k_zero<<<1, 32>>>();
    k_stats<<<RB, 128>>>(feat);
    k_deg<<<RB, 256>>>(mask);
    k_finalize<<<1, 128>>>(gamma, beta);
    k_scatter<<<RB, 256>>>(mask);
    k_norm<<<(NN * DD / 4 + 255) / 256, 256>>>(feat);
    k_gi<<<dim3(NT, 3), 256, SMEMB>>>(W_ih, b_ih);
    k_step0<<<(NN + 1) / 2, 256>>>(src, b_hh);
    for (int t = 1; t < MD; ++t) {
        k_gh<<<dim3(NT, 3), 256, SMEMB>>>(W_hh, t);
        k_gate<<<(NN + 1) / 2, 256>>>(src, b_hh, t);
    }
    k_final<<<NT, 256, SMEMB>>>(W_self, W_neigh, out);
}